// round 6
// baseline (speedup 1.0000x reference)
#include <cuda_runtime.h>
#include <cstdint>

#define NB 4
#define NL 512
#define ND 128
#define L2E 1.4426950408889634f

// Scratch (static device arrays)
__device__ float g_a [NB*NL*ND];     // 1 MB
__device__ float g_bm[NB*NL*ND];     // 1 MB
__device__ float g_sc[NB*NL*NL];     // 4 MB raw scores
__device__ float g_ms [NB*NL];       // per-(b,j): max_i(score) * log2(e)
__device__ float g_inv[NB*NL];       // per-(b,j): 1 / sum_i exp

__device__ __forceinline__ float tanh_fast(float x) {
    float y; asm("tanh.approx.f32 %0, %1;" : "=f"(y) : "f"(x)); return y;
}
__device__ __forceinline__ float ex2_fast(float x) {
    float y; asm("ex2.approx.ftz.f32 %0, %1;" : "=f"(y) : "f"(x)); return y;
}
__device__ __forceinline__ float rcp_fast(float x) {
    float y; asm("rcp.approx.ftz.f32 %0, %1;" : "=f"(y) : "f"(x)); return y;
}

// ---------------------------------------------------------------------------
// Kernel A: projections (transposed weight contraction):
//   a [bl][e] = sum_d hs[bl][d] * W_attn[e, d]
//   bm[bl][e] = sum_d hs[bl][d] * W_attn[e, 128 + d]
// grid (64 row-tiles, 4 chunks of the 256 fused outputs), 256 threads.
// W read coalesced along d; stored transposed with additive swizzle
// (col' = (c+d) & 63) -> pitch 64, conflict-free reads AND writes. 48 KB smem.
// ---------------------------------------------------------------------------
__global__ void proj_kernel(const float* __restrict__ hs,
                            const float* __restrict__ W) {
    __shared__ float hs_s[32 * 128];    // 16 KB
    __shared__ float W_s [128 * 64];    // 32 KB, [d][swizzled c]
    const int rowbase = blockIdx.x * 32;
    const int colbase = blockIdx.y * 64;
    const int tid = threadIdx.x;

    for (int k = tid; k < 32 * 128; k += 256)
        hs_s[k] = hs[(rowbase + (k >> 7)) * 128 + (k & 127)];
    // Coalesced: consecutive tid -> consecutive d.
    for (int k = tid; k < 64 * 128; k += 256) {
        int c = k >> 7, d = k & 127;
        int e = colbase + c;
        float w = (e < 128) ? W[e * 256 + d] : W[(e - 128) * 256 + 128 + d];
        W_s[d * 64 + ((c + d) & 63)] = w;
    }
    __syncthreads();

    const int ty = tid >> 5, tx = tid & 31;
    float acc[4][2] = {};
#pragma unroll 4
    for (int k = 0; k < 128; k++) {
        float w0 = W_s[k * 64 + ((tx      + k) & 63)];
        float w1 = W_s[k * 64 + ((tx + 32 + k) & 63)];
#pragma unroll
        for (int rr = 0; rr < 4; rr++) {
            float h = hs_s[(ty * 4 + rr) * 128 + k];   // warp broadcast
            acc[rr][0] += h * w0;
            acc[rr][1] += h * w1;
        }
    }
#pragma unroll
    for (int rr = 0; rr < 4; rr++) {
        int row = rowbase + ty * 4 + rr;
#pragma unroll
        for (int cc = 0; cc < 2; cc++) {
            int e = colbase + tx + cc * 32;
            float val = acc[rr][cc];
            if (e < 128) g_a [row * 128 + e]         = val;
            else         g_bm[row * 128 + (e - 128)] = val;
        }
    }
}

// ---------------------------------------------------------------------------
// Kernel B (MUFU-bound): scores[b,i,j] = sum_d v[d]*tanh(a[b,i,d]+bm[b,j,d])
// grid (16,16,4), 256 threads, 2x2 micro-tile, float4 smem (pitch 33 vec4)
// ---------------------------------------------------------------------------
__global__ void score_kernel(const float* __restrict__ v) {
    __shared__ float4 a_s[32 * 33];     // 16.9 KB, row pitch 33 float4
    __shared__ float4 b_s[32 * 33];
    __shared__ float4 v_s[32];
    const int bi = blockIdx.z;
    const int i0 = blockIdx.x * 32, j0 = blockIdx.y * 32;
    const int tid = threadIdx.x;

    const float4* ga4 = (const float4*)g_a;
    const float4* gb4 = (const float4*)g_bm;
    for (int k = tid; k < 32 * 32; k += 256) {
        int r = k >> 5, q = k & 31;
        a_s[r * 33 + q] = ga4[(bi * NL + i0 + r) * 32 + q];
        b_s[r * 33 + q] = gb4[(bi * NL + j0 + r) * 32 + q];
    }
    if (tid < 32) v_s[tid] = ((const float4*)v)[tid];
    __syncthreads();

    const int ty = tid >> 4, tx = tid & 15;
    float acc00 = 0.f, acc01 = 0.f, acc10 = 0.f, acc11 = 0.f;
#pragma unroll 8
    for (int q = 0; q < 32; q++) {
        float4 vq = v_s[q];
        float4 a0 = a_s[ ty       * 33 + q];
        float4 a1 = a_s[(ty + 16) * 33 + q];
        float4 b0 = b_s[ tx       * 33 + q];
        float4 b1 = b_s[(tx + 16) * 33 + q];
        acc00 += vq.x * tanh_fast(a0.x + b0.x);
        acc00 += vq.y * tanh_fast(a0.y + b0.y);
        acc00 += vq.z * tanh_fast(a0.z + b0.z);
        acc00 += vq.w * tanh_fast(a0.w + b0.w);
        acc01 += vq.x * tanh_fast(a0.x + b1.x);
        acc01 += vq.y * tanh_fast(a0.y + b1.y);
        acc01 += vq.z * tanh_fast(a0.z + b1.z);
        acc01 += vq.w * tanh_fast(a0.w + b1.w);
        acc10 += vq.x * tanh_fast(a1.x + b0.x);
        acc10 += vq.y * tanh_fast(a1.y + b0.y);
        acc10 += vq.z * tanh_fast(a1.z + b0.z);
        acc10 += vq.w * tanh_fast(a1.w + b0.w);
        acc11 += vq.x * tanh_fast(a1.x + b1.x);
        acc11 += vq.y * tanh_fast(a1.y + b1.y);
        acc11 += vq.z * tanh_fast(a1.z + b1.z);
        acc11 += vq.w * tanh_fast(a1.w + b1.w);
    }
    float* sp = g_sc + (size_t)bi * NL * NL;
    sp[(i0 + ty     ) * NL + j0 + tx     ] = acc00;
    sp[(i0 + ty     ) * NL + j0 + tx + 16] = acc01;
    sp[(i0 + ty + 16) * NL + j0 + tx     ] = acc10;
    sp[(i0 + ty + 16) * NL + j0 + tx + 16] = acc11;
}

// ---------------------------------------------------------------------------
// Kernel C: per-(b,j) softmax stats over i (axis=1). Writes m* = max*log2e
// and inv = 1/sum(exp). No normalize pass; out_kernel reconstructs weights.
// grid (16, 4), 256 threads: 32 j-cols x 8 i-groups per block.
// ---------------------------------------------------------------------------
__global__ void stat_kernel() {
    const int bi = blockIdx.y;
    const int l  = threadIdx.x & 31;         // j lane
    const int g  = threadIdx.x >> 5;         // i-group 0..7
    const int j  = blockIdx.x * 32 + l;
    const float* sp = g_sc + (size_t)bi * NL * NL + j;
    __shared__ float red[8][32];

    float m = -1e30f;
#pragma unroll 8
    for (int i = g; i < NL; i += 8) m = fmaxf(m, sp[i * NL]);
    red[g][l] = m;
    __syncthreads();
    if (g == 0) {
#pragma unroll
        for (int r = 1; r < 8; r++) m = fmaxf(m, red[r][l]);
        red[0][l] = m;
    }
    __syncthreads();
    const float ms = red[0][l] * L2E;

    float s = 0.f;
#pragma unroll 8
    for (int i = g; i < NL; i += 8) s += ex2_fast(sp[i * NL] * L2E - ms);
    __syncthreads();
    red[g][l] = s;
    __syncthreads();
    if (g == 0) {
#pragma unroll
        for (int r = 1; r < 8; r++) s += red[r][l];
        g_ms [bi * NL + j] = ms;
        g_inv[bi * NL + j] = rcp_fast(s);
    }
}

// ---------------------------------------------------------------------------
// Kernel D v2: out[b,i,d] = sum_j softmax_w[b,i,j] * hs[b,j,d]
// h kept in REGISTERS (32 float2 per thread, coalesced LDG per chunk);
// only w goes through smem (warp-broadcast reads). Grid 256 blocks so every
// SM holds 2 CTAs (latency hiding). 16 i-rows x 64 d per block.
// Thread: 2 i-rows x 1 d-pair. smem = 12 KB.
// ---------------------------------------------------------------------------
__global__ void __launch_bounds__(256, 2)
out_kernel(const float* __restrict__ hs, float* __restrict__ out) {
    __shared__ float ms_s [NL];          // 2 KB
    __shared__ float inv_s[NL];          // 2 KB
    __shared__ float w_s[2][16 * 32];    // 4 KB (double-buffered w tile)
    const int i0 = blockIdx.x * 16;
    const int bi = blockIdx.y;
    const int d0 = blockIdx.z * 64;
    const int tid = threadIdx.x;
    const int ty = tid >> 5;             // warp id = i-row pair (0..7)
    const int tx = tid & 31;             // d-pair lane

    for (int k = tid; k < NL; k += 256) {
        ms_s [k] = g_ms [bi * NL + k];
        inv_s[k] = g_inv[bi * NL + k];
    }

    const float* scb  = g_sc + (size_t)bi * NL * NL;
    const float* hsb  = hs + (bi * NL) * ND + d0 + tx * 2;

    // ---- prologue: w chunk 0 ----
    float rw[2];
#pragma unroll
    for (int s = 0; s < 2; s++) {
        int k = tid + 256 * s;                    // k = row*32 + j
        rw[s] = scb[(i0 + (k >> 5)) * NL + (k & 31)];
    }
    // h regs chunk 0 (32 independent coalesced LDG.64)
    float2 hreg[32];
#pragma unroll
    for (int j = 0; j < 32; j++)
        hreg[j] = *(const float2*)&hsb[j * ND];
    __syncthreads();                              // ms_s/inv_s visible
#pragma unroll
    for (int s = 0; s < 2; s++) {
        int k = tid + 256 * s;
        int jl = k & 31;
        w_s[0][k] = ex2_fast(rw[s] * L2E - ms_s[jl]) * inv_s[jl];
    }
    __syncthreads();

    float2 acc0 = make_float2(0.f, 0.f);
    float2 acc1 = make_float2(0.f, 0.f);

    int p = 0;
    for (int c = 0; c < 16; c++) {
        const int jn = (c + 1) * 32;
        if (c < 15) {
            // prefetch next w (regs) — LDG latency covered by compute below
#pragma unroll
            for (int s = 0; s < 2; s++) {
                int k = tid + 256 * s;
                rw[s] = scb[(i0 + (k >> 5)) * NL + jn + (k & 31)];
            }
        }

        // compute current chunk: w broadcasts from smem, h from regs
        const float* wp = w_s[p];
#pragma unroll 8
        for (int j = 0; j < 32; j++) {
            float w0 = wp[(ty * 2    ) * 32 + j];   // warp broadcast
            float w1 = wp[(ty * 2 + 1) * 32 + j];   // warp broadcast
            acc0.x += w0 * hreg[j].x;  acc0.y += w0 * hreg[j].y;
            acc1.x += w1 * hreg[j].x;  acc1.y += w1 * hreg[j].y;
        }

        if (c < 15) {
            // reload h regs for next chunk (regs now free)
#pragma unroll
            for (int j = 0; j < 32; j++)
                hreg[j] = *(const float2*)&hsb[(jn + j) * ND];
            // transform prefetched w into the other buffer
#pragma unroll
            for (int s = 0; s < 2; s++) {
                int k = tid + 256 * s;
                int jl = k & 31;
                w_s[p ^ 1][k] = ex2_fast(rw[s] * L2E - ms_s[jn + jl]) * inv_s[jn + jl];
            }
            __syncthreads();
        }
        p ^= 1;
    }

    float* ob = out + ((size_t)bi * NL + i0 + ty * 2) * ND + d0 + tx * 2;
    *(float2*)&ob[0]  = acc0;
    *(float2*)&ob[ND] = acc1;
}

// ---------------------------------------------------------------------------
extern "C" void kernel_launch(void* const* d_in, const int* in_sizes, int n_in,
                              void* d_out, int out_size) {
    const float* hs = (const float*)d_in[0];   // (4,512,128)
    const float* W  = (const float*)d_in[1];   // (128,256)
    const float* v  = (const float*)d_in[2];   // (128,)
    float* out = (float*)d_out;                // (4,512,128)

    proj_kernel <<<dim3(64, 4),     256>>>(hs, W);
    score_kernel<<<dim3(16, 16, 4), 256>>>(v);
    stat_kernel <<<dim3(16, 4),     256>>>();
    out_kernel  <<<dim3(32, 4, 2),  256>>>(hs, out);
}

// round 7
// speedup vs baseline: 1.5607x; 1.5607x over previous
#include <cuda_runtime.h>
#include <cstdint>

#define NB 4
#define NL 512
#define ND 128
#define L2E 1.4426950408889634f

// Scratch (static device arrays)
__device__ float g_a [NB*NL*ND];     // 1 MB
__device__ float g_bm[NB*NL*ND];     // 1 MB
__device__ float g_sc[NB*NL*NL];     // 4 MB raw scores
__device__ float g_ms [NB*NL];       // per-(b,j): max_i(score) * log2(e)
__device__ float g_inv[NB*NL];       // per-(b,j): 1 / sum_i exp

__device__ __forceinline__ float tanh_fast(float x) {
    float y; asm("tanh.approx.f32 %0, %1;" : "=f"(y) : "f"(x)); return y;
}
__device__ __forceinline__ float ex2_fast(float x) {
    float y; asm("ex2.approx.ftz.f32 %0, %1;" : "=f"(y) : "f"(x)); return y;
}
__device__ __forceinline__ float rcp_fast(float x) {
    float y; asm("rcp.approx.ftz.f32 %0, %1;" : "=f"(y) : "f"(x)); return y;
}
__device__ __forceinline__ void cp_async16(unsigned int dst, const void* src) {
    asm volatile("cp.async.cg.shared.global [%0], [%1], 16;\n" :: "r"(dst), "l"(src));
}
__device__ __forceinline__ unsigned int smem_u32(const void* p) {
    unsigned int a;
    asm("{ .reg .u64 t; cvta.to.shared.u64 t, %1; cvt.u32.u64 %0, t; }" : "=r"(a) : "l"(p));
    return a;
}

// ---------------------------------------------------------------------------
// Kernel A: projections (transposed weight contraction):
//   a [bl][e] = sum_d hs[bl][d] * W_attn[e, d]
//   bm[bl][e] = sum_d hs[bl][d] * W_attn[e, 128 + d]
// grid (64 row-tiles, 4 chunks of the 256 fused outputs), 256 threads.
// ---------------------------------------------------------------------------
__global__ void proj_kernel(const float* __restrict__ hs,
                            const float* __restrict__ W) {
    __shared__ float hs_s[32 * 128];    // 16 KB
    __shared__ float W_s [128 * 64];    // 32 KB, [d][swizzled c]
    const int rowbase = blockIdx.x * 32;
    const int colbase = blockIdx.y * 64;
    const int tid = threadIdx.x;

    for (int k = tid; k < 32 * 128; k += 256)
        hs_s[k] = hs[(rowbase + (k >> 7)) * 128 + (k & 127)];
    for (int k = tid; k < 64 * 128; k += 256) {
        int c = k >> 7, d = k & 127;
        int e = colbase + c;
        float w = (e < 128) ? W[e * 256 + d] : W[(e - 128) * 256 + 128 + d];
        W_s[d * 64 + ((c + d) & 63)] = w;
    }
    __syncthreads();

    const int ty = tid >> 5, tx = tid & 31;
    float acc[4][2] = {};
#pragma unroll 4
    for (int k = 0; k < 128; k++) {
        float w0 = W_s[k * 64 + ((tx      + k) & 63)];
        float w1 = W_s[k * 64 + ((tx + 32 + k) & 63)];
#pragma unroll
        for (int rr = 0; rr < 4; rr++) {
            float h = hs_s[(ty * 4 + rr) * 128 + k];   // warp broadcast
            acc[rr][0] += h * w0;
            acc[rr][1] += h * w1;
        }
    }
#pragma unroll
    for (int rr = 0; rr < 4; rr++) {
        int row = rowbase + ty * 4 + rr;
#pragma unroll
        for (int cc = 0; cc < 2; cc++) {
            int e = colbase + tx + cc * 32;
            float val = acc[rr][cc];
            if (e < 128) g_a [row * 128 + e]         = val;
            else         g_bm[row * 128 + (e - 128)] = val;
        }
    }
}

// ---------------------------------------------------------------------------
// Kernel B (MUFU-bound): scores[b,i,j] = sum_d v[d]*tanh(a[b,i,d]+bm[b,j,d])
// grid (16,16,4), 256 threads, 2x2 micro-tile, float4 smem (pitch 33 vec4)
// ---------------------------------------------------------------------------
__global__ void score_kernel(const float* __restrict__ v) {
    __shared__ float4 a_s[32 * 33];     // 16.9 KB, row pitch 33 float4
    __shared__ float4 b_s[32 * 33];
    __shared__ float4 v_s[32];
    const int bi = blockIdx.z;
    const int i0 = blockIdx.x * 32, j0 = blockIdx.y * 32;
    const int tid = threadIdx.x;

    const float4* ga4 = (const float4*)g_a;
    const float4* gb4 = (const float4*)g_bm;
    for (int k = tid; k < 32 * 32; k += 256) {
        int r = k >> 5, q = k & 31;
        a_s[r * 33 + q] = ga4[(bi * NL + i0 + r) * 32 + q];
        b_s[r * 33 + q] = gb4[(bi * NL + j0 + r) * 32 + q];
    }
    if (tid < 32) v_s[tid] = ((const float4*)v)[tid];
    __syncthreads();

    const int ty = tid >> 4, tx = tid & 15;
    float acc00 = 0.f, acc01 = 0.f, acc10 = 0.f, acc11 = 0.f;
#pragma unroll 8
    for (int q = 0; q < 32; q++) {
        float4 vq = v_s[q];
        float4 a0 = a_s[ ty       * 33 + q];
        float4 a1 = a_s[(ty + 16) * 33 + q];
        float4 b0 = b_s[ tx       * 33 + q];
        float4 b1 = b_s[(tx + 16) * 33 + q];
        acc00 += vq.x * tanh_fast(a0.x + b0.x);
        acc00 += vq.y * tanh_fast(a0.y + b0.y);
        acc00 += vq.z * tanh_fast(a0.z + b0.z);
        acc00 += vq.w * tanh_fast(a0.w + b0.w);
        acc01 += vq.x * tanh_fast(a0.x + b1.x);
        acc01 += vq.y * tanh_fast(a0.y + b1.y);
        acc01 += vq.z * tanh_fast(a0.z + b1.z);
        acc01 += vq.w * tanh_fast(a0.w + b1.w);
        acc10 += vq.x * tanh_fast(a1.x + b0.x);
        acc10 += vq.y * tanh_fast(a1.y + b0.y);
        acc10 += vq.z * tanh_fast(a1.z + b0.z);
        acc10 += vq.w * tanh_fast(a1.w + b0.w);
        acc11 += vq.x * tanh_fast(a1.x + b1.x);
        acc11 += vq.y * tanh_fast(a1.y + b1.y);
        acc11 += vq.z * tanh_fast(a1.z + b1.z);
        acc11 += vq.w * tanh_fast(a1.w + b1.w);
    }
    float* sp = g_sc + (size_t)bi * NL * NL;
    sp[(i0 + ty     ) * NL + j0 + tx     ] = acc00;
    sp[(i0 + ty     ) * NL + j0 + tx + 16] = acc01;
    sp[(i0 + ty + 16) * NL + j0 + tx     ] = acc10;
    sp[(i0 + ty + 16) * NL + j0 + tx + 16] = acc11;
}

// ---------------------------------------------------------------------------
// Kernel C: per-(b,j) softmax stats over i (axis=1). Writes m* = max*log2e
// and inv = 1/sum(exp). out_kernel reconstructs weights on the fly.
// ---------------------------------------------------------------------------
__global__ void stat_kernel() {
    const int bi = blockIdx.y;
    const int l  = threadIdx.x & 31;         // j lane
    const int g  = threadIdx.x >> 5;         // i-group 0..7
    const int j  = blockIdx.x * 32 + l;
    const float* sp = g_sc + (size_t)bi * NL * NL + j;
    __shared__ float red[8][32];

    float m = -1e30f;
#pragma unroll 8
    for (int i = g; i < NL; i += 8) m = fmaxf(m, sp[i * NL]);
    red[g][l] = m;
    __syncthreads();
    if (g == 0) {
#pragma unroll
        for (int r = 1; r < 8; r++) m = fmaxf(m, red[r][l]);
        red[0][l] = m;
    }
    __syncthreads();
    const float ms = red[0][l] * L2E;

    float s = 0.f;
#pragma unroll 8
    for (int i = g; i < NL; i += 8) s += ex2_fast(sp[i * NL] * L2E - ms);
    __syncthreads();
    red[g][l] = s;
    __syncthreads();
    if (g == 0) {
#pragma unroll
        for (int r = 1; r < 8; r++) s += red[r][l];
        g_ms [bi * NL + j] = ms;
        g_inv[bi * NL + j] = rcp_fast(s);
    }
}

// ---------------------------------------------------------------------------
// Kernel D v3: out[b,i,d] = sum_j softmax_w[b,i,j] * hs[b,j,d]
// GEMM fragment layout. Block: 32 i x 64 d, 256 threads.
// Warp wid covers all 32 rows x 8 d (d-seg = wid*8).
// Lane (r = lane>>1, c = lane&1): thread = 2 rows (2r,2r+1) x float4 (c*4).
// Per j per warp: 1 LDS.64 w-frag (128B distinct, 1 cyc) +
//                 1 LDS.128 h-frag (32B distinct, 1 cyc) + 8 FFMA  -> FMA-bound.
// w staged transposed [j][34] (aligned, conflict-free); h double-buffered via
// cp.async. w reconstructed from raw scores with softmax stats. smem 29 KB.
// ---------------------------------------------------------------------------
__global__ void __launch_bounds__(256, 2)
out_kernel(const float* __restrict__ hs, float* __restrict__ out) {
    __shared__ float ms_s [NL];                       // 2 KB
    __shared__ float inv_s[NL];                       // 2 KB
    __shared__ float w_s[2][32 * 34];                 // 8.5 KB  [j][row] pitch 34
    __shared__ __align__(16) float h_s[2][32 * 64];   // 16 KB   [j][d]
    const int i0 = blockIdx.x * 32;
    const int bi = blockIdx.y;
    const int d0 = blockIdx.z * 64;
    const int tid  = threadIdx.x;
    const int wid  = tid >> 5;
    const int lane = tid & 31;
    const int r = lane >> 1;          // row-pair index 0..15
    const int c = lane & 1;           // float4 column 0..1
    const int dfrag = wid * 8 + c * 4;

    for (int k = tid; k < NL; k += 256) {
        ms_s [k] = g_ms [bi * NL + k];
        inv_s[k] = g_inv[bi * NL + k];
    }

    const float* scb = g_sc + (size_t)bi * NL * NL;

    // ---- prologue: chunk 0 ----
    float rw[4];
#pragma unroll
    for (int s = 0; s < 4; s++) {
        int k = tid + 256 * s;                 // k = row*32 + j  (coalesced over j)
        rw[s] = scb[(i0 + (k >> 5)) * NL + (k & 31)];
    }
#pragma unroll
    for (int s = 0; s < 2; s++) {
        int k = tid + 256 * s;                 // k = j*16 + seg
        int j = k >> 4, seg = k & 15;
        cp_async16(smem_u32(&h_s[0][j * 64 + seg * 4]),
                   &hs[(bi * NL + j) * ND + d0 + seg * 4]);
    }
    asm volatile("cp.async.commit_group;\n" ::: "memory");
    __syncthreads();                            // ms_s/inv_s visible
#pragma unroll
    for (int s = 0; s < 4; s++) {
        int k = tid + 256 * s;
        int row = k >> 5, j = k & 31;
        w_s[0][j * 34 + row] = ex2_fast(rw[s] * L2E - ms_s[j]) * inv_s[j];
    }
    asm volatile("cp.async.wait_group 0;\n" ::: "memory");
    __syncthreads();

    float4 acc0 = make_float4(0.f, 0.f, 0.f, 0.f);
    float4 acc1 = make_float4(0.f, 0.f, 0.f, 0.f);

    int p = 0;
    for (int ch = 0; ch < 16; ch++) {
        const int jn = (ch + 1) * 32;
        if (ch < 15) {
            // prefetch next raw w (coalesced) + next h (cp.async, other buffer)
#pragma unroll
            for (int s = 0; s < 4; s++) {
                int k = tid + 256 * s;
                rw[s] = scb[(i0 + (k >> 5)) * NL + jn + (k & 31)];
            }
#pragma unroll
            for (int s = 0; s < 2; s++) {
                int k = tid + 256 * s;
                int j = k >> 4, seg = k & 15;
                cp_async16(smem_u32(&h_s[p ^ 1][j * 64 + seg * 4]),
                           &hs[(bi * NL + jn + j) * ND + d0 + seg * 4]);
            }
            asm volatile("cp.async.commit_group;\n" ::: "memory");
        }

        // compute current chunk
        const float* wp = w_s[p];
        const float* hp = h_s[p];
#pragma unroll 8
        for (int j = 0; j < 32; j++) {
            float2 wf = *(const float2*)&wp[j * 34 + r * 2];   // 128B/warp
            float4 hf = *(const float4*)&hp[j * 64 + dfrag];   // 32B/warp
            acc0.x += wf.x * hf.x;  acc0.y += wf.x * hf.y;
            acc0.z += wf.x * hf.z;  acc0.w += wf.x * hf.w;
            acc1.x += wf.y * hf.x;  acc1.y += wf.y * hf.y;
            acc1.z += wf.y * hf.z;  acc1.w += wf.y * hf.w;
        }

        if (ch < 15) {
#pragma unroll
            for (int s = 0; s < 4; s++) {
                int k = tid + 256 * s;
                int row = k >> 5, j = k & 31;
                w_s[p ^ 1][j * 34 + row] =
                    ex2_fast(rw[s] * L2E - ms_s[jn + j]) * inv_s[jn + j];
            }
            asm volatile("cp.async.wait_group 0;\n" ::: "memory");
            __syncthreads();
        }
        p ^= 1;
    }

    float* ob = out + ((size_t)bi * NL + i0 + r * 2) * ND + d0 + dfrag;
    *(float4*)&ob[0]  = acc0;
    *(float4*)&ob[ND] = acc1;
}

// ---------------------------------------------------------------------------
extern "C" void kernel_launch(void* const* d_in, const int* in_sizes, int n_in,
                              void* d_out, int out_size) {
    const float* hs = (const float*)d_in[0];   // (4,512,128)
    const float* W  = (const float*)d_in[1];   // (128,256)
    const float* v  = (const float*)d_in[2];   // (128,)
    float* out = (float*)d_out;                // (4,512,128)

    proj_kernel <<<dim3(64, 4),     256>>>(hs, W);
    score_kernel<<<dim3(16, 16, 4), 256>>>(v);
    stat_kernel <<<dim3(16, 4),     256>>>();
    out_kernel  <<<dim3(16, 4, 2),  256>>>(hs, out);
}